// round 1
// baseline (speedup 1.0000x reference)
#include <cuda_runtime.h>
#include <cstdint>

#define BB 1024
#define TT 128
#define KK 128
#define KP 132            // padded transT row (float4-aligned, conflict-free)
#define START_TAG (KK-2)
#define STOP_TAG  (KK-1)

struct SmemLayout {
    float transT[KK * KP];        // transT[cur*KP + prev] = trans[prev*KK + cur]
    float part[2][KK];            // double-buffered partition
    float lastpart[KK];           // partition snapshot at t = L-1
    float vals[KK];               // final reduction scratch
    int   dec[TT];                // decoded path
    unsigned char bp[TT][KK];     // bp[i][cur] = backpointer for step t=i+1
};

__global__ void __launch_bounds__(128, 2)
viterbi_kernel(const float* __restrict__ feats,
               const float* __restrict__ trans,
               const void*  __restrict__ masks,
               float* __restrict__ out)
{
    extern __shared__ __align__(16) unsigned char smem_raw[];
    SmemLayout& s = *reinterpret_cast<SmemLayout*>(smem_raw);

    const int b   = blockIdx.x;
    const int tid = threadIdx.x;   // = cur tag

    // ---- load transposed transitions into shared (one-time, coalesced read) ----
    for (int i = tid; i < KK * KK; i += 128) {
        int prev = i >> 7;
        int cur  = i & 127;
        s.transT[cur * KP + prev] = trans[i];
    }

    // ---- mask dtype auto-detect + per-batch length via syncthreads_count ----
    // lengths >= T/2 = 64, so masks[b][1] is always true. Byte layout => byte[1]==1;
    // int32 little-endian layout => byte[1]==0.
    const unsigned char* mbytes = (const unsigned char*)masks;
    bool bytemode = (mbytes[1] == 1);
    bool my_mask;
    if (bytemode) my_mask = (mbytes[(size_t)b * TT + tid] != 0);
    else          my_mask = (((const int*)masks)[(size_t)b * TT + tid] != 0);
    const int L = __syncthreads_count(my_mask);   // also barriers the transT load

    // ---- init partition: t = 0 ----
    const float* fb = feats + (size_t)b * TT * KK;
    {
        float f0 = fb[tid];
        float p0 = __fadd_rn(f0, s.transT[tid * KP + START_TAG]);
        s.part[0][tid] = p0;
        if (L == 1) s.lastpart[tid] = p0;    // defensive (L>=64 in practice)
    }
    __syncthreads();

    // ---- forward recursion t = 1..T-1 ----
    const float NEG_INF = __int_as_float(0xff800000);
    float featnext = fb[KK + tid];
    int pcur = 0;

    for (int t = 1; t < TT; ++t) {
        const float feat = featnext;
        if (t + 1 < TT) featnext = fb[(size_t)(t + 1) * KK + tid];

        const float4* tr4 = reinterpret_cast<const float4*>(&s.transT[tid * KP]);
        const float4* p4  = reinterpret_cast<const float4*>(s.part[pcur]);

        float m = NEG_INF;
        int   idx = 0;

#pragma unroll
        for (int q = 0; q < 32; ++q) {
            float4 tv = tr4[q];
            float4 pv = p4[q];
            float v0 = __fadd_rn(__fadd_rn(pv.x, tv.x), feat);
            if (v0 > m) { m = v0; idx = 4 * q + 0; }
            float v1 = __fadd_rn(__fadd_rn(pv.y, tv.y), feat);
            if (v1 > m) { m = v1; idx = 4 * q + 1; }
            float v2 = __fadd_rn(__fadd_rn(pv.z, tv.z), feat);
            if (v2 > m) { m = v2; idx = 4 * q + 2; }
            float v3 = __fadd_rn(__fadd_rn(pv.w, tv.w), feat);
            if (v3 > m) { m = v3; idx = 4 * q + 3; }
        }

        s.part[pcur ^ 1][tid] = m;
        s.bp[t - 1][tid] = (unsigned char)((t < L) ? idx : 0);
        if (t == L - 1) s.lastpart[tid] = m;
        pcur ^= 1;
        __syncthreads();
    }

    // ---- STOP transition: pointer + path_score (exact first-index argmax) ----
    {
        float v = __fadd_rn(s.lastpart[tid], s.transT[STOP_TAG * KP + tid]);
        s.vals[tid] = v;
    }
    __syncthreads();

    if (tid == 0) {
        float m = s.vals[0];
        int ptr = 0;
        for (int p = 1; p < KK; ++p) {
            float vv = s.vals[p];
            if (vv > m) { m = vv; ptr = p; }
        }
        out[b] = m;  // path_score

        // ---- backtrace (all in shared) ----
        s.dec[TT - 1] = ptr;
        int cur = ptr;
        for (int i = TT - 2; i >= 0; --i) {
            int np = (i == L - 1) ? ptr : (int)s.bp[i][cur];
            s.dec[i] = np;
            cur = np;
        }
    }
    __syncthreads();

    // decode_idx as float32 (coalesced write)
    out[BB + (size_t)b * TT + tid] = (float)s.dec[tid];
}

extern "C" void kernel_launch(void* const* d_in, const int* in_sizes, int n_in,
                              void* d_out, int out_size)
{
    const float* feats = (const float*)d_in[0];
    const float* trans = (const float*)d_in[1];
    const void*  masks = d_in[2];
    float* out = (float*)d_out;

    cudaFuncSetAttribute(viterbi_kernel,
                         cudaFuncAttributeMaxDynamicSharedMemorySize,
                         (int)sizeof(SmemLayout));
    viterbi_kernel<<<BB, 128, sizeof(SmemLayout)>>>(feats, trans, masks, out);
}

// round 2
// speedup vs baseline: 1.3938x; 1.3938x over previous
#include <cuda_runtime.h>
#include <cstdint>

#define BB 1024
#define TT 128
#define KK 128
#define START_TAG (KK-2)
#define STOP_TAG  (KK-1)

struct SmemLayout {
    float part[2][KK];            // double-buffered partition
    int   dec[TT];                // decoded path
    unsigned char bp[TT][KK];     // bp[i][cur] = backpointer for forward step t=i+1
};

#define CHAIN4(vsrc, tj, base)                                        \
    {                                                                 \
        float v;                                                      \
        v = __fadd_rn(__fadd_rn((vsrc).x, treg[(tj)+0]), feat);       \
        if (v > m##base) { m##base = v; i##base = (tj)+0; }           \
        v = __fadd_rn(__fadd_rn((vsrc).y, treg[(tj)+1]), feat);       \
        if (v > m##base) { m##base = v; i##base = (tj)+1; }           \
        v = __fadd_rn(__fadd_rn((vsrc).z, treg[(tj)+2]), feat);       \
        if (v > m##base) { m##base = v; i##base = (tj)+2; }           \
        v = __fadd_rn(__fadd_rn((vsrc).w, treg[(tj)+3]), feat);       \
        if (v > m##base) { m##base = v; i##base = (tj)+3; }           \
    }

__global__ void __launch_bounds__(128, 3)
viterbi_kernel(const float* __restrict__ feats,
               const float* __restrict__ trans,
               const void*  __restrict__ masks,
               float* __restrict__ out)
{
    extern __shared__ __align__(16) unsigned char smem_raw[];
    SmemLayout& s = *reinterpret_cast<SmemLayout*>(smem_raw);

    const int b   = blockIdx.x;
    const int tid = threadIdx.x;   // = cur tag

    // ---- transitions column tid -> registers: treg[p] = trans[p][tid] ----
    float treg[KK];
#pragma unroll
    for (int p = 0; p < KK; ++p)
        treg[p] = trans[p * KK + tid];   // coalesced across threads

    // ---- mask dtype auto-detect + per-batch length ----
    const unsigned char* mbytes = (const unsigned char*)masks;
    bool bytemode = (mbytes[1] == 1);    // lengths >= 64 -> masks[0][1] true
    bool my_mask;
    if (bytemode) my_mask = (mbytes[(size_t)b * TT + tid] != 0);
    else          my_mask = (((const int*)masks)[(size_t)b * TT + tid] != 0);
    const int L = __syncthreads_count(my_mask);

    // ---- t = 0 init ----
    const float* fb = feats + (size_t)b * TT * KK;
    s.part[0][tid] = __fadd_rn(fb[tid], treg[START_TAG]);
    __syncthreads();

    // ---- forward recursion t = 1..L-1 (early exit: rest is dead work) ----
    const float NEG_INF = __int_as_float(0xff800000);
    float featnext = fb[KK + tid];
    int pcur = 0;

    for (int t = 1; t < L; ++t) {
        const float feat = featnext;
        if (t + 1 < TT) featnext = fb[(size_t)(t + 1) * KK + tid];

        const float4* p4 = reinterpret_cast<const float4*>(s.part[pcur]);

        // 4 independent chains over contiguous ranges (exact first-index argmax)
        float m0 = NEG_INF, m1 = NEG_INF, m2 = NEG_INF, m3 = NEG_INF;
        int   i0 = 0, i1 = 32, i2 = 64, i3 = 96;

#pragma unroll
        for (int q = 0; q < 8; ++q) {
            float4 a = p4[q];        // broadcast (uniform address)
            float4 bq = p4[8 + q];
            float4 c = p4[16 + q];
            float4 d = p4[24 + q];
            CHAIN4(a,  4 * q,       0)
            CHAIN4(bq, 32 + 4 * q,  1)
            CHAIN4(c,  64 + 4 * q,  2)
            CHAIN4(d,  96 + 4 * q,  3)
        }

        // merge: strict >, left-preferred => global first-index argmax
        float m = m0; int idx = i0;
        if (m1 > m) { m = m1; idx = i1; }
        if (m2 > m) { m = m2; idx = i2; }
        if (m3 > m) { m = m3; idx = i3; }

        s.part[pcur ^ 1][tid] = m;
        s.bp[t - 1][tid] = (unsigned char)idx;
        pcur ^= 1;
        __syncthreads();
    }
    // s.part[pcur] now holds partition at step L-1 (== last_partition)

    // ---- STOP transition + backtrace, by thread 127 (owns trans[:, STOP]) ----
    if (tid == STOP_TAG) {
        const float* lp = s.part[pcur];
        float m0 = NEG_INF, m1 = NEG_INF, m2 = NEG_INF, m3 = NEG_INF;
        int   i0 = 0, i1 = 32, i2 = 64, i3 = 96;
#pragma unroll
        for (int p = 0; p < 32; ++p) {
            float v;
            v = __fadd_rn(lp[p],      treg[p]);       if (v > m0) { m0 = v; i0 = p; }
            v = __fadd_rn(lp[32 + p], treg[32 + p]);  if (v > m1) { m1 = v; i1 = 32 + p; }
            v = __fadd_rn(lp[64 + p], treg[64 + p]);  if (v > m2) { m2 = v; i2 = 64 + p; }
            v = __fadd_rn(lp[96 + p], treg[96 + p]);  if (v > m3) { m3 = v; i3 = 96 + p; }
        }
        float m = m0; int ptr = i0;
        if (m1 > m) { m = m1; ptr = i1; }
        if (m2 > m) { m = m2; ptr = i2; }
        if (m3 > m) { m = m3; ptr = i3; }

        out[b] = m;                       // path_score

        // decode: positions [L, T-2] are zeros, L-1 and T-1 are ptr,
        // 0..L-2 follow the stored backpointers.
        s.dec[TT - 1] = ptr;
        for (int i = TT - 2; i >= L; --i) s.dec[i] = 0;
        if (L - 1 <= TT - 2) s.dec[L - 1] = ptr;
        int cur = ptr;
        for (int i = L - 2; i >= 0; --i) {
            cur = (int)s.bp[i][cur];
            s.dec[i] = cur;
        }
    }
    __syncthreads();

    // decode_idx as float32 (coalesced)
    out[BB + (size_t)b * TT + tid] = (float)s.dec[tid];
}

extern "C" void kernel_launch(void* const* d_in, const int* in_sizes, int n_in,
                              void* d_out, int out_size)
{
    const float* feats = (const float*)d_in[0];
    const float* trans = (const float*)d_in[1];
    const void*  masks = d_in[2];
    float* out = (float*)d_out;

    viterbi_kernel<<<BB, 128, sizeof(SmemLayout)>>>(feats, trans, masks, out);
}

// round 3
// speedup vs baseline: 1.5805x; 1.1340x over previous
#include <cuda_runtime.h>
#include <cstdint>

#define BB 1024
#define TT 128
#define KK 128
#define TSTRIDE 130           // even (8B pair alignment), padded row
#define START_TAG (KK-2)
#define STOP_TAG  (KK-1)

struct SmemLayout {
    float transT[KK * TSTRIDE];   // transT[cur*TSTRIDE + prev] = trans[prev*KK + cur]
    float part[2][KK];            // double-buffered partition
    int   dec[TT];
    unsigned char bp[TT][KK];     // bp[i][cur], forward step t = i+1
};

__device__ __forceinline__ unsigned long long add2(unsigned long long a, unsigned long long b) {
    unsigned long long r;
    asm("add.rn.f32x2 %0, %1, %2;" : "=l"(r) : "l"(a), "l"(b));
    return r;
}
__device__ __forceinline__ unsigned long long pack2(float lo, float hi) {
    unsigned long long r;
    asm("mov.b64 %0, {%1, %2};" : "=l"(r) : "f"(lo), "f"(hi));
    return r;
}
__device__ __forceinline__ float lo_f(unsigned long long v) { return __uint_as_float((unsigned)v); }
__device__ __forceinline__ float hi_f(unsigned long long v) { return __uint_as_float((unsigned)(v >> 32)); }

__global__ void __launch_bounds__(256, 2)
viterbi_kernel(const float* __restrict__ feats,
               const float* __restrict__ trans,
               const void*  __restrict__ masks,
               float* __restrict__ out)
{
    extern __shared__ __align__(16) unsigned char smem_raw[];
    SmemLayout& s = *reinterpret_cast<SmemLayout*>(smem_raw);

    const int b   = blockIdx.x;
    const int tid = threadIdx.x;
    const int cur = tid >> 1;     // tag handled by this thread pair
    const int h   = tid & 1;      // half of prev range: h=0 -> prevs 0..63, h=1 -> 64..127

    // ---- transT fill (one-time, coalesced global read) ----
    for (int i = tid; i < KK * KK; i += 256) {
        int prev = i >> 7, c = i & 127;
        s.transT[c * TSTRIDE + prev] = trans[i];
    }

    // ---- mask dtype auto-detect + length ----
    const unsigned char* mbytes = (const unsigned char*)masks;
    bool bytemode = (mbytes[1] == 1);          // lengths >= 64 => masks[0][1] true
    bool my_mask = false;
    if (tid < TT) {
        if (bytemode) my_mask = (mbytes[(size_t)b * TT + tid] != 0);
        else          my_mask = (((const int*)masks)[(size_t)b * TT + tid] != 0);
    }
    const int L = __syncthreads_count(my_mask);   // also barriers transT fill

    // ---- treg: 32 packed pairs = this thread's 64 prev transitions ----
    unsigned long long treg[32];
    {
        const float* myrow = &s.transT[cur * TSTRIDE + h * 64];
#pragma unroll
        for (int j = 0; j < 32; ++j)
            treg[j] = *reinterpret_cast<const unsigned long long*>(&myrow[2 * j]);
    }

    // ---- t = 0 init ----
    const float* fb = feats + (size_t)b * TT * KK;
    if (h == 0)
        s.part[0][cur] = __fadd_rn(fb[cur], s.transT[cur * TSTRIDE + START_TAG]);
    __syncthreads();

    const float NEG_INF = __int_as_float(0xff800000);
    float featnext = fb[KK + cur];
    int pcur = 0;

    // ---- forward recursion t = 1..L-1 ----
    for (int t = 1; t < L; ++t) {
        const float feat = featnext;
        featnext = fb[(size_t)(t + 1 < TT ? t + 1 : t) * KK + cur];
        const unsigned long long feat2 = pack2(feat, feat);

        const float4* p4 = reinterpret_cast<const float4*>(&s.part[pcur][h * 64]);

        // 4 chains x 8 pairs, contiguous ascending ranges
        float mch[4]; int jch[4];
#pragma unroll
        for (int c = 0; c < 4; ++c) { mch[c] = NEG_INF; jch[c] = c * 8; }

#pragma unroll
        for (int c = 0; c < 4; ++c) {
#pragma unroll
            for (int q = 0; q < 4; ++q) {
                float4 pv = p4[c * 4 + q];            // broadcast LDS.128
                const int j0 = c * 8 + q * 2;
                unsigned long long va = add2(add2(pack2(pv.x, pv.y), treg[j0]),     feat2);
                unsigned long long vb = add2(add2(pack2(pv.z, pv.w), treg[j0 + 1]), feat2);
                float pma = fmaxf(lo_f(va), hi_f(va));
                if (pma > mch[c]) { mch[c] = pma; jch[c] = j0; }
                float pmb = fmaxf(lo_f(vb), hi_f(vb));
                if (pmb > mch[c]) { mch[c] = pmb; jch[c] = j0 + 1; }
            }
        }
        // merge chains left-to-right, strict > (first-index)
        float mm = mch[0]; int jj = jch[0];
        if (mch[1] > mm) { mm = mch[1]; jj = jch[1]; }
        if (mch[2] > mm) { mm = mch[2]; jj = jch[2]; }
        if (mch[3] > mm) { mm = mch[3]; jj = jch[3]; }

        // exchange with the other half (partner lane = lane^1)
        float om = __shfl_xor_sync(0xffffffffu, mm, 1);
        int   oj = __shfl_xor_sync(0xffffffffu, jj, 1);

        if (h == 0) {
            // global winner: lower half preferred on tie (strict >)
            int wh = 0; float wm = mm; int wj = jj;
            if (om > mm) { wm = om; wj = oj; wh = 1; }
            // recover which half of the winning pair (bit-exact recompute)
            const int pbase = wh * 64 + wj * 2;
            unsigned long long t2 = *reinterpret_cast<const unsigned long long*>(
                                        &s.transT[cur * TSTRIDE + pbase]);
            unsigned long long p2 = *reinterpret_cast<const unsigned long long*>(
                                        &s.part[pcur][pbase]);
            unsigned long long v2 = add2(add2(p2, t2), feat2);
            const int idx = pbase + ((hi_f(v2) > lo_f(v2)) ? 1 : 0);

            s.part[pcur ^ 1][cur] = wm;
            s.bp[t - 1][cur] = (unsigned char)idx;
        }
        pcur ^= 1;
        __syncthreads();
    }
    // s.part[pcur] holds partition at step L-1 (== last_partition)

    // ---- STOP transition + backtrace (single thread; tiny) ----
    if (tid == 0) {
        const float* lp = s.part[pcur];
        const float* ts = &s.transT[STOP_TAG * TSTRIDE];  // trans[prev][STOP]
        float m0 = NEG_INF, m1 = NEG_INF, m2 = NEG_INF, m3 = NEG_INF;
        int   i0 = 0, i1 = 32, i2 = 64, i3 = 96;
#pragma unroll
        for (int p = 0; p < 32; ++p) {
            float v;
            v = __fadd_rn(lp[p],      ts[p]);       if (v > m0) { m0 = v; i0 = p; }
            v = __fadd_rn(lp[32 + p], ts[32 + p]);  if (v > m1) { m1 = v; i1 = 32 + p; }
            v = __fadd_rn(lp[64 + p], ts[64 + p]);  if (v > m2) { m2 = v; i2 = 64 + p; }
            v = __fadd_rn(lp[96 + p], ts[96 + p]);  if (v > m3) { m3 = v; i3 = 96 + p; }
        }
        float m = m0; int ptr = i0;
        if (m1 > m) { m = m1; ptr = i1; }
        if (m2 > m) { m = m2; ptr = i2; }
        if (m3 > m) { m = m3; ptr = i3; }

        out[b] = m;                        // path_score

        s.dec[TT - 1] = ptr;
        for (int i = TT - 2; i >= L; --i) s.dec[i] = 0;
        if (L - 1 <= TT - 2) s.dec[L - 1] = ptr;
        int c = ptr;
        for (int i = L - 2; i >= 0; --i) {
            c = (int)s.bp[i][c];
            s.dec[i] = c;
        }
    }
    __syncthreads();

    if (tid < TT)
        out[BB + (size_t)b * TT + tid] = (float)s.dec[tid];
}

extern "C" void kernel_launch(void* const* d_in, const int* in_sizes, int n_in,
                              void* d_out, int out_size)
{
    const float* feats = (const float*)d_in[0];
    const float* trans = (const float*)d_in[1];
    const void*  masks = d_in[2];
    float* out = (float*)d_out;

    cudaFuncSetAttribute(viterbi_kernel,
                         cudaFuncAttributeMaxDynamicSharedMemorySize,
                         (int)sizeof(SmemLayout));
    viterbi_kernel<<<BB, 256, sizeof(SmemLayout)>>>(feats, trans, masks, out);
}